// round 8
// baseline (speedup 1.0000x reference)
#include <cuda_runtime.h>

#define NEGV (-1000000000.0f)
#define NEGH (-5.0e8f)

static constexpr int Bb   = 8;
static constexpr int Nn   = 6000;
static constexpr int Cc   = 21;
static constexpr int MAXT = 200;
static constexpr int TS   = 256;      // NMS block size
static constexpr int NW   = TS / 32;  // 8 warps
static constexpr int CAP  = 1024;     // per-chunk sort capacity
static constexpr int NB   = 256;      // score histogram buckets
static constexpr int CHUNK_TGT = 400; // typical candidates needed before 200 sels

// ------------------------- scratch (device globals; no allocs) -------------
__device__ float4 g_boxes [Bb * Cc * Nn];
__device__ float  g_scores[Bb * Cc * Nn];
__device__ float  g_selval[Bb * Cc * MAXT];
__device__ float4 g_selbox[Bb * Cc * MAXT];

// ------------------------- kernel 1: decode + score (bit-exact, proven) ----
__global__ void k_decode(const float* __restrict__ roi,
                         const float* __restrict__ deltas,
                         const float* __restrict__ probs)
{
    int i = blockIdx.x * blockDim.x + threadIdx.x;   // (b*N + n)
    if (i >= Bb * Nn) return;
    int b = i / Nn;
    int n = i - b * Nn;

    const float* p = probs + (size_t)i * Cc;
    float pv[Cc];
#pragma unroll
    for (int c = 0; c < Cc; c++) pv[c] = p[c];
    float best = pv[0];
    int   lbl  = 0;
#pragma unroll
    for (int c = 1; c < Cc; c++) {
        if (pv[c] > best) { best = pv[c]; lbl = c; }
    }

    float4 r  = *(const float4*)(roi + (size_t)i * 4);
    float ah = __fsub_rn(r.z, r.x);
    float aw = __fsub_rn(r.w, r.y);
    float cy = __fmaf_rn(0.5f, ah, r.x);
    float cx = __fmaf_rn(0.5f, aw, r.y);

    const float4* d4 = (const float4*)(deltas + (size_t)i * Cc * 4);
#pragma unroll
    for (int c = 0; c < Cc; c++) {
        float4 d  = d4[c];
        float dy = __fmul_rn(d.x, 0.1f);
        float dx = __fmul_rn(d.y, 0.1f);
        float dh = __fmul_rn(d.z, 0.2f);
        float dw = __fmul_rn(d.w, 0.2f);
        float bh  = __fmul_rn(expf(dh), ah);
        float bw  = __fmul_rn(expf(dw), aw);
        float bcy = __fmaf_rn(dy, ah, cy);
        float bcx = __fmaf_rn(dx, aw, cx);
        float y1 = __fmaf_rn(-0.5f, bh, bcy);
        float x1 = __fmaf_rn(-0.5f, bw, bcx);
        float y2 = __fadd_rn(y1, bh);
        float x2 = __fadd_rn(x1, bw);
        y1 = fminf(fmaxf(y1, 0.f), 1.f);
        x1 = fminf(fmaxf(x1, 0.f), 1.f);
        y2 = fminf(fmaxf(y2, 0.f), 1.f);
        x2 = fminf(fmaxf(x2, 0.f), 1.f);

        float sc = (lbl != 0) ? pv[c] : 0.f;
        sc = (sc > 0.5f) ? sc : NEGV;

        size_t base = (size_t)(b * Cc + c) * Nn + n; // [B][C][N]
        g_scores[base] = sc;
        if (sc > NEGH)
            g_boxes[base] = make_float4(y1, x1, y2, x2);
    }
}

// ------------------------- IoU decision, div-free common path --------------
// Returns exactly (__fdiv_rn(inter,denom) > 0.5f) for the reference formula.
__device__ __forceinline__ bool iou_gt_fast(const float4 sb, const float sa,
                                            const float4 cb, const float ca)
{
    float iy1 = fmaxf(sb.x, cb.x);
    float ix1 = fmaxf(sb.y, cb.y);
    float iy2 = fminf(sb.z, cb.z);
    float ix2 = fminf(sb.w, cb.w);
    float inter = __fmul_rn(fmaxf(__fsub_rn(iy2, iy1), 0.f),
                            fmaxf(__fsub_rn(ix2, ix1), 0.f));
    if (!(inter > 0.f)) return false;           // q = 0, denom >= 1e-8 > 0
    float denom = __fadd_rn(__fsub_rn(__fadd_rn(sa, ca), inter), 1e-8f);
    float a2 = __fadd_rn(inter, inter);         // 2*inter, exact
    // conservative filter: q > 0.50004 -> rn(q) > 0.5 ; q < 0.49996 -> not
    if (a2 > __fmul_rn(denom, 1.0001f)) return true;
    if (a2 < __fmul_rn(denom, 0.9999f)) return false;
    return __fdiv_rn(inter, denom) > 0.5f;      // rare exact fallback
}

// ------------------------- kernel 2: chunked sorted greedy NMS -------------
__global__ void __launch_bounds__(TS) k_nms()
{
    const int c  = blockIdx.x;
    const int b  = blockIdx.y;
    const int bc = b * Cc + c;
    const float*  sc_g = g_scores + (size_t)bc * Nn;
    const float4* bx_g = g_boxes  + (size_t)bc * Nn;

    __shared__ unsigned long long s_key[CAP];    // (score_bits<<32)|(Nn-n): desc
    __shared__ int      s_hist[NB];
    __shared__ int      s_cnt;
    __shared__ int      s_lo;
    __shared__ int      s_nsel;
    __shared__ float4   s_selB[MAXT];
    __shared__ float    s_selA[MAXT];
    __shared__ float4   s_cb[TS];                // compacted alive candidates
    __shared__ float    s_ca[TS];
    __shared__ float    s_cs[TS];
    __shared__ int      s_wcnt[NW];

    const int tid  = threadIdx.x;
    const int lane = tid & 31;
    const int wid  = tid >> 5;

    for (int i = tid; i < NB; i += TS) s_hist[i] = 0;
    if (tid == 0) s_nsel = 0;
    __syncthreads();

    // histogram of candidate score buckets (scores in (0.5,1): exponent fixed,
    // (bits>>15)&0xFF is monotone in score)
    for (int n = tid; n < Nn; n += TS) {
        float sc = sc_g[n];
        if (sc > NEGH)
            atomicAdd(&s_hist[(__float_as_uint(sc) >> 15) & 0xFF], 1);
    }
    __syncthreads();

    float*  outv = g_selval + (size_t)bc * MAXT;
    float4* outb = g_selbox + (size_t)bc * MAXT;

    int nsel = 0;
    int hiB  = NB;                               // exclusive upper bucket

    while (nsel < MAXT && hiB > 0) {
        if (tid == 0) {
            int cum = 0, lo = hiB;
            while (lo > 0) {
                int cnt = s_hist[lo - 1];
                if (cum + cnt > CAP && cum > 0) break;
                cum += cnt;
                lo--;
                if (cum > CAP) break;            // single huge bucket: clamp
                if (cum >= CHUNK_TGT) break;     // enough for typical 200 sels
            }
            s_lo  = lo;
            s_cnt = 0;
        }
        __syncthreads();
        const int loB = s_lo;
        __syncthreads();

        for (int n = tid; n < Nn; n += TS) {     // collect chunk
            float sc = sc_g[n];
            if (sc > NEGH) {
                unsigned bits = __float_as_uint(sc);
                int bk = (bits >> 15) & 0xFF;
                if (bk >= loB && bk < hiB) {
                    int pos = atomicAdd(&s_cnt, 1);
                    if (pos < CAP)
                        s_key[pos] = ((unsigned long long)bits << 32)
                                   | (unsigned int)(Nn - n);
                }
            }
        }
        __syncthreads();
        int cntc = s_cnt;
        if (cntc > CAP) cntc = CAP;

        if (cntc > 0) {
            int M = 2;
            while (M < cntc) M <<= 1;
            for (int i = cntc + tid; i < M; i += TS) s_key[i] = 0ull;
            __syncthreads();
            for (int k = 2; k <= M; k <<= 1) {
                for (int j = k >> 1; j > 0; j >>= 1) {
                    for (int i = tid; i < M; i += TS) {
                        int ixj = i ^ j;
                        if (ixj > i) {
                            unsigned long long a = s_key[i], bb = s_key[ixj];
                            bool desc = ((i & k) == 0);
                            if (desc ? (a < bb) : (a > bb)) { s_key[i] = bb; s_key[ixj] = a; }
                        }
                    }
                    __syncthreads();
                }
            }

            // ---- batched walk: parallel pre-check, warp-0 in-order funnel ----
            for (int p0 = 0; p0 < cntc && nsel < MAXT; p0 += TS) {
                int p = p0 + tid;
                bool has = (p < cntc);
                float4 cb = make_float4(0.f, 0.f, 0.f, 0.f);
                float  ca = 0.f, csc = 0.f;
                if (has) {
                    unsigned long long key = s_key[p];
                    int n = Nn - (int)(unsigned int)(key & 0xFFFFFFFFull);
                    cb  = bx_g[n];
                    ca  = __fmul_rn(fmaxf(__fsub_rn(cb.z, cb.x), 0.f),
                                    fmaxf(__fsub_rn(cb.w, cb.y), 0.f));
                    csc = __uint_as_float((unsigned int)(key >> 32));
                }
                bool alive = has;
                for (int s = 0; s < nsel && alive; s++)       // vs prior selections
                    if (iou_gt_fast(s_selB[s], s_selA[s], cb, ca)) alive = false;

                // order-preserving block compaction of alive candidates
                unsigned wm = __ballot_sync(0xffffffffu, alive);
                if (lane == 0) s_wcnt[wid] = __popc(wm);
                __syncthreads();
                int base = 0, total = 0;
#pragma unroll
                for (int w = 0; w < NW; w++) {
                    int v = s_wcnt[w];
                    if (w < wid) base += v;
                    total += v;
                }
                if (alive) {
                    int off = base + __popc(wm & ((1u << lane) - 1u));
                    s_cb[off] = cb; s_ca[off] = ca; s_cs[off] = csc;
                }
                __syncthreads();

                // warp 0 resolves the compacted list in order (shfl rounds)
                if (wid == 0 && total > 0) {
                    int ns = nsel;
                    const int batchStart = nsel;
                    for (int g0 = 0; g0 < total && ns < MAXT; g0 += 32) {
                        int idx = g0 + lane;
                        bool mine = (idx < total);
                        float4 c2b = make_float4(0.f, 0.f, 0.f, 0.f);
                        float  c2a = 0.f, c2s = 0.f;
                        if (mine) { c2b = s_cb[idx]; c2a = s_ca[idx]; c2s = s_cs[idx]; }
                        __syncwarp();
                        bool al = mine;
                        for (int s = batchStart; s < ns && al; s++)   // in-batch sels
                            if (iou_gt_fast(s_selB[s], s_selA[s], c2b, c2a)) al = false;
                        while (ns < MAXT) {
                            unsigned m = __ballot_sync(0xffffffffu, al);
                            if (!m) break;
                            int l = __ffs(m) - 1;
                            float4 sb;
                            sb.x = __shfl_sync(0xffffffffu, c2b.x, l);
                            sb.y = __shfl_sync(0xffffffffu, c2b.y, l);
                            sb.z = __shfl_sync(0xffffffffu, c2b.z, l);
                            sb.w = __shfl_sync(0xffffffffu, c2b.w, l);
                            float sa = __shfl_sync(0xffffffffu, c2a, l);
                            if (lane == l) {
                                outv[ns]   = c2s;
                                outb[ns]   = c2b;
                                s_selB[ns] = c2b;
                                s_selA[ns] = c2a;
                                al = false;
                            }
                            ns++;
                            if (al && iou_gt_fast(sb, sa, c2b, c2a)) al = false;
                        }
                        __syncwarp();            // s_selB writes visible in-warp
                    }
                    if (lane == 0) s_nsel = ns;
                }
                __syncthreads();
                nsel = s_nsel;
            }
        }
        hiB = loB;
        __syncthreads();                         // s_cnt reuse safe
    }

    for (int t = nsel + tid; t < MAXT; t += TS) outv[t] = NEGV;
}

// ------------------------- kernel 3: merge 21 sorted lists -> top-200 ------
__global__ void __launch_bounds__(256) k_topk(float* __restrict__ out)
{
    const int c = blockIdx.x;
    const int b = blockIdx.y;
    __shared__ float s_val[Cc * MAXT];
    __shared__ int   s_Vc[Cc];

    const float* gv = g_selval + (size_t)b * Cc * MAXT;
    for (int j = threadIdx.x; j < Cc * MAXT; j += blockDim.x) s_val[j] = gv[j];
    __syncthreads();

    if (threadIdx.x < Cc) {
        const float* L = s_val + threadIdx.x * MAXT;
        int lo = 0, hi = MAXT;
        while (lo < hi) { int m = (lo + hi) >> 1; if (L[m] > NEGH) lo = m + 1; else hi = m; }
        s_Vc[threadIdx.x] = lo;
    }
    __syncthreads();

    float* ob = out + (size_t)b * MAXT * 4;                         // bboxes [B,200,4]
    float* ol = out + (size_t)Bb * MAXT * 4 + (size_t)b * MAXT;     // labels [B,200]
    float* os = out + (size_t)Bb * MAXT * 5 + (size_t)b * MAXT;     // scores [B,200]

    if (c == 0) {   // zero-fill tail rows once per image
        int V = 0;
#pragma unroll
        for (int cc = 0; cc < Cc; cc++) V += s_Vc[cc];
        for (int r = V + (int)threadIdx.x; r < MAXT; r += blockDim.x) {
            os[r] = 0.f; ol[r] = 0.f;
            ((float4*)ob)[r] = make_float4(0.f, 0.f, 0.f, 0.f);
        }
    }

    int t = threadIdx.x;
    if (t < s_Vc[c]) {
        float v = s_val[c * MAXT + t];
        int rank = t;
#pragma unroll 1
        for (int c2 = 0; c2 < Cc; c2++) {
            if (c2 == c) continue;
            const float* L = s_val + c2 * MAXT;
            int lo = 0, hi = s_Vc[c2];
            if (c2 < c) {
                while (lo < hi) { int m = (lo + hi) >> 1; if (L[m] >= v) lo = m + 1; else hi = m; }
            } else {
                while (lo < hi) { int m = (lo + hi) >> 1; if (L[m] >  v) lo = m + 1; else hi = m; }
            }
            rank += lo;
        }
        if (rank < MAXT) {
            os[rank] = v;
            ol[rank] = (float)c;
            ((float4*)ob)[rank] = g_selbox[(size_t)b * Cc * MAXT + c * MAXT + t];
        }
    }
}

// ------------------------- launch ------------------------------------------
extern "C" void kernel_launch(void* const* d_in, const int* in_sizes, int n_in,
                              void* d_out, int out_size)
{
    const float* roi    = (const float*)d_in[0];
    const float* deltas = (const float*)d_in[1];
    const float* probs  = (const float*)d_in[2];
    float* out = (float*)d_out;

    k_decode<<<(Bb * Nn + 127) / 128, 128>>>(roi, deltas, probs);
    dim3 g2(Cc, Bb);
    k_nms<<<g2, TS>>>();
    k_topk<<<g2, 256>>>(out);
}

// round 9
// speedup vs baseline: 2.3671x; 2.3671x over previous
#include <cuda_runtime.h>

#define NEGV (-1000000000.0f)
#define NEGH (-5.0e8f)

static constexpr int Bb   = 8;
static constexpr int Nn   = 6000;
static constexpr int Cc   = 21;
static constexpr int MAXT = 200;
static constexpr int TS   = 256;      // NMS block size
static constexpr int NW   = TS / 32;  // 8 warps
static constexpr int CAP  = 1024;     // per-chunk sort capacity
static constexpr int NB   = 256;      // score histogram buckets

// ------------------------- scratch (device globals; no allocs) -------------
__device__ float4 g_boxes [Bb * Cc * Nn];
__device__ float  g_scores[Bb * Cc * Nn];
__device__ float  g_selval[Bb * Cc * MAXT];
__device__ float4 g_selbox[Bb * Cc * MAXT];

// ------------------------- kernel 1: decode + score (bit-exact, proven) ----
__global__ void k_decode(const float* __restrict__ roi,
                         const float* __restrict__ deltas,
                         const float* __restrict__ probs)
{
    int i = blockIdx.x * blockDim.x + threadIdx.x;   // (b*N + n)
    if (i >= Bb * Nn) return;
    int b = i / Nn;
    int n = i - b * Nn;

    const float* p = probs + (size_t)i * Cc;
    float pv[Cc];
#pragma unroll
    for (int c = 0; c < Cc; c++) pv[c] = p[c];
    float best = pv[0];
    int   lbl  = 0;
#pragma unroll
    for (int c = 1; c < Cc; c++) {
        if (pv[c] > best) { best = pv[c]; lbl = c; }
    }

    float4 r  = *(const float4*)(roi + (size_t)i * 4);
    float ah = __fsub_rn(r.z, r.x);
    float aw = __fsub_rn(r.w, r.y);
    float cy = __fmaf_rn(0.5f, ah, r.x);
    float cx = __fmaf_rn(0.5f, aw, r.y);

    const float4* d4 = (const float4*)(deltas + (size_t)i * Cc * 4);
#pragma unroll
    for (int c = 0; c < Cc; c++) {
        float4 d  = d4[c];
        float dy = __fmul_rn(d.x, 0.1f);
        float dx = __fmul_rn(d.y, 0.1f);
        float dh = __fmul_rn(d.z, 0.2f);
        float dw = __fmul_rn(d.w, 0.2f);
        float bh  = __fmul_rn(expf(dh), ah);
        float bw  = __fmul_rn(expf(dw), aw);
        float bcy = __fmaf_rn(dy, ah, cy);
        float bcx = __fmaf_rn(dx, aw, cx);
        float y1 = __fmaf_rn(-0.5f, bh, bcy);
        float x1 = __fmaf_rn(-0.5f, bw, bcx);
        float y2 = __fadd_rn(y1, bh);
        float x2 = __fadd_rn(x1, bw);
        y1 = fminf(fmaxf(y1, 0.f), 1.f);
        x1 = fminf(fmaxf(x1, 0.f), 1.f);
        y2 = fminf(fmaxf(y2, 0.f), 1.f);
        x2 = fminf(fmaxf(x2, 0.f), 1.f);

        float sc = (lbl != 0) ? pv[c] : 0.f;
        sc = (sc > 0.5f) ? sc : NEGV;

        size_t base = (size_t)(b * Cc + c) * Nn + n; // [B][C][N]
        g_scores[base] = sc;
        if (sc > NEGH)
            g_boxes[base] = make_float4(y1, x1, y2, x2);
    }
}

// ------------------------- IoU decision, mostly branch/div-free ------------
// Returns exactly (__fdiv_rn(inter,denom) > 0.5f) for the reference formula.
// 2*inter vs denom*(1 +/- 1e-4): margin >> 1 ulp, so outside the band the
// decision equals the rounded-division compare; exact fallback only in band.
__device__ __forceinline__ bool iou_gt_fast(const float4 sb, const float sa,
                                            const float4 cb, const float ca)
{
    float iy1 = fmaxf(sb.x, cb.x);
    float ix1 = fmaxf(sb.y, cb.y);
    float iy2 = fminf(sb.z, cb.z);
    float ix2 = fminf(sb.w, cb.w);
    float inter = __fmul_rn(fmaxf(__fsub_rn(iy2, iy1), 0.f),
                            fmaxf(__fsub_rn(ix2, ix1), 0.f));
    float denom = __fadd_rn(__fsub_rn(__fadd_rn(sa, ca), inter), 1e-8f);
    float a2 = __fadd_rn(inter, inter);
    bool gt = a2 > __fmul_rn(denom, 1.0001f);
    bool lt = a2 < __fmul_rn(denom, 0.9999f);   // inter==0 lands here (denom>0)
    if (!gt && !lt)                              // rare: ~1e-4 of evals
        gt = __fdiv_rn(inter, denom) > 0.5f;
    return gt;
}

// ------------------------- kernel 2: chunked sorted greedy NMS -------------
// Scores in (0.5,1): exponent fixed -> (bits>>15)&0xFF monotone 8-bit bucket.
// Process buckets top-down in chunks of <=CAP; sort chunk; greedy walk with
// persistent selection state. Identical order to a full sort.
__global__ void __launch_bounds__(TS) k_nms()
{
    const int c  = blockIdx.x;
    const int b  = blockIdx.y;
    const int bc = b * Cc + c;
    const float*  sc_g = g_scores + (size_t)bc * Nn;
    const float4* bx_g = g_boxes  + (size_t)bc * Nn;

    __shared__ unsigned long long s_key[CAP];    // (score_bits<<32)|(Nn-n): desc
    __shared__ int      s_hist[NB];
    __shared__ int      s_cnt;
    __shared__ int      s_lo;
    __shared__ float4   s_selB[MAXT];
    __shared__ float    s_selA[MAXT];
    __shared__ float4   s_wbox[2][NW];
    __shared__ float    s_wa  [2][NW];
    __shared__ float    s_ws  [2][NW];
    __shared__ unsigned s_wm  [2][NW];

    const int tid  = threadIdx.x;
    const int lane = tid & 31;
    const int wid  = tid >> 5;

    for (int i = tid; i < NB; i += TS) s_hist[i] = 0;
    __syncthreads();

    for (int n = tid; n < Nn; n += TS) {
        float sc = sc_g[n];
        if (sc > NEGH)
            atomicAdd(&s_hist[(__float_as_uint(sc) >> 15) & 0xFF], 1);
    }
    __syncthreads();

    float*  outv = g_selval + (size_t)bc * MAXT;
    float4* outb = g_selbox + (size_t)bc * MAXT;

    int nsel = 0;
    int par  = 0;
    int hiB  = NB;                                // exclusive upper bucket

    while (nsel < MAXT && hiB > 0) {
        if (tid == 0) {
            int cum = 0, lo = hiB;
            while (lo > 0) {
                int cnt = s_hist[lo - 1];
                if (cum + cnt > CAP && cum > 0) break;
                cum += cnt;
                lo--;
                if (cum > CAP) break;            // single huge bucket: clamp
            }
            s_lo  = lo;
            s_cnt = 0;
        }
        __syncthreads();
        const int loB = s_lo;
        __syncthreads();

        for (int n = tid; n < Nn; n += TS) {     // collect chunk
            float sc = sc_g[n];
            if (sc > NEGH) {
                unsigned bits = __float_as_uint(sc);
                int bk = (bits >> 15) & 0xFF;
                if (bk >= loB && bk < hiB) {
                    int pos = atomicAdd(&s_cnt, 1);
                    if (pos < CAP)
                        s_key[pos] = ((unsigned long long)bits << 32)
                                   | (unsigned int)(Nn - n);
                }
            }
        }
        __syncthreads();
        int cntc = s_cnt;
        if (cntc > CAP) cntc = CAP;

        if (cntc > 0) {
            int M = 2;
            while (M < cntc) M <<= 1;
            for (int i = cntc + tid; i < M; i += TS) s_key[i] = 0ull;
            __syncthreads();
            for (int k = 2; k <= M; k <<= 1) {
                for (int j = k >> 1; j > 0; j >>= 1) {
                    for (int i = tid; i < M; i += TS) {
                        int ixj = i ^ j;
                        if (ixj > i) {
                            unsigned long long a = s_key[i], bb = s_key[ixj];
                            bool desc = ((i & k) == 0);
                            if (desc ? (a < bb) : (a > bb)) { s_key[i] = bb; s_key[ixj] = a; }
                        }
                    }
                    __syncthreads();
                }
            }

            // batched greedy walk over this chunk
            for (int p0 = 0; p0 < cntc && nsel < MAXT; p0 += TS) {
                int p = p0 + tid;
                bool has = (p < cntc);
                float4 cb = make_float4(0.f, 0.f, 0.f, 0.f);
                float  ca = 0.f, csc = 0.f;
                if (has) {
                    unsigned long long key = s_key[p];
                    int n = Nn - (int)(unsigned int)(key & 0xFFFFFFFFull);
                    cb  = bx_g[n];
                    ca  = __fmul_rn(fmaxf(__fsub_rn(cb.z, cb.x), 0.f),
                                    fmaxf(__fsub_rn(cb.w, cb.y), 0.f));
                    csc = __uint_as_float((unsigned int)(key >> 32));
                }
                // branch-free pre-check vs all prior selections (pipelined)
                bool dead = false;
#pragma unroll 4
                for (int s = 0; s < nsel; s++)
                    dead |= iou_gt_fast(s_selB[s], s_selA[s], cb, ca);
                bool alive = has && !dead;

                // in-order resolution within batch (one round per selection)
                while (nsel < MAXT) {
                    unsigned wm = __ballot_sync(0xffffffffu, alive);
                    if (wm && lane == (unsigned)(__ffs(wm) - 1)) {
                        s_wbox[par][wid] = cb;
                        s_wa  [par][wid] = ca;
                        s_ws  [par][wid] = csc;
                    }
                    if (lane == 0) s_wm[par][wid] = wm;
                    __syncthreads();
                    bool mylive = (lane < NW) && (s_wm[par][lane] != 0u);
                    unsigned havew = __ballot_sync(0xffffffffu, mylive);
                    if (!havew) break;                 // uniform
                    int w = __ffs(havew) - 1;
                    float4 sb = s_wbox[par][w];
                    float  sa = s_wa  [par][w];
                    int winner = (w << 5) + (__ffs(s_wm[par][w]) - 1);
                    if (tid == winner) {
                        outv[nsel]   = s_ws[par][w];
                        outb[nsel]   = sb;
                        s_selB[nsel] = sb;
                        s_selA[nsel] = sa;
                        alive = false;
                    }
                    nsel++;                            // uniform
                    par ^= 1;
                    if (alive && iou_gt_fast(sb, sa, cb, ca)) alive = false;
                }
                __syncthreads();                       // selections visible
            }
        }
        hiB = loB;
        __syncthreads();                               // s_cnt reuse safe
    }

    for (int t = nsel + tid; t < MAXT; t += TS) outv[t] = NEGV;
}

// ------------------------- kernel 3: merge 21 sorted lists -> top-200 ------
__global__ void __launch_bounds__(256) k_topk(float* __restrict__ out)
{
    const int c = blockIdx.x;
    const int b = blockIdx.y;
    __shared__ float s_val[Cc * MAXT];
    __shared__ int   s_Vc[Cc];

    const float* gv = g_selval + (size_t)b * Cc * MAXT;
    for (int j = threadIdx.x; j < Cc * MAXT; j += blockDim.x) s_val[j] = gv[j];
    __syncthreads();

    if (threadIdx.x < Cc) {
        const float* L = s_val + threadIdx.x * MAXT;
        int lo = 0, hi = MAXT;
        while (lo < hi) { int m = (lo + hi) >> 1; if (L[m] > NEGH) lo = m + 1; else hi = m; }
        s_Vc[threadIdx.x] = lo;
    }
    __syncthreads();

    float* ob = out + (size_t)b * MAXT * 4;                         // bboxes [B,200,4]
    float* ol = out + (size_t)Bb * MAXT * 4 + (size_t)b * MAXT;     // labels [B,200]
    float* os = out + (size_t)Bb * MAXT * 5 + (size_t)b * MAXT;     // scores [B,200]

    if (c == 0) {   // zero-fill tail rows once per image
        int V = 0;
#pragma unroll
        for (int cc = 0; cc < Cc; cc++) V += s_Vc[cc];
        for (int r = V + (int)threadIdx.x; r < MAXT; r += blockDim.x) {
            os[r] = 0.f; ol[r] = 0.f;
            ((float4*)ob)[r] = make_float4(0.f, 0.f, 0.f, 0.f);
        }
    }

    int t = threadIdx.x;
    if (t < s_Vc[c]) {
        float v = s_val[c * MAXT + t];
        int rank = t;
#pragma unroll 1
        for (int c2 = 0; c2 < Cc; c2++) {
            if (c2 == c) continue;
            const float* L = s_val + c2 * MAXT;
            int lo = 0, hi = s_Vc[c2];
            if (c2 < c) {
                while (lo < hi) { int m = (lo + hi) >> 1; if (L[m] >= v) lo = m + 1; else hi = m; }
            } else {
                while (lo < hi) { int m = (lo + hi) >> 1; if (L[m] >  v) lo = m + 1; else hi = m; }
            }
            rank += lo;
        }
        if (rank < MAXT) {
            os[rank] = v;
            ol[rank] = (float)c;
            ((float4*)ob)[rank] = g_selbox[(size_t)b * Cc * MAXT + c * MAXT + t];
        }
    }
}

// ------------------------- launch ------------------------------------------
extern "C" void kernel_launch(void* const* d_in, const int* in_sizes, int n_in,
                              void* d_out, int out_size)
{
    const float* roi    = (const float*)d_in[0];
    const float* deltas = (const float*)d_in[1];
    const float* probs  = (const float*)d_in[2];
    float* out = (float*)d_out;

    k_decode<<<(Bb * Nn + 127) / 128, 128>>>(roi, deltas, probs);
    dim3 g2(Cc, Bb);
    k_nms<<<g2, TS>>>();
    k_topk<<<g2, 256>>>(out);
}